// round 14
// baseline (speedup 1.0000x reference)
#include <cuda_runtime.h>
#include <cuda_bf16.h>

// PSAvgPooling: B=8, H=W=64, C=1152 (= 9 bins * 128), N=512 boxes/image,
// 3x3 bins x 3x3 crop samples, bilinear gather, weighted bin-average.
//
// R13 = R12 resubmit (R13 bench error was container infra; kernel never ran).
// R12: L2-BANDWIDTH model. R1/R2d/R7 all sit at 490MB distinct L2 traffic
// / ~6300 B/cyc LTS cap ~= 74k cyc; R10/R11 load-count changes were no-ops
// because they didn't change distinct bytes. This round attacks bytes:
//   1) tiny kernel bucket-sorts boxes by (image, 8x8 spatial bucket)
//   2) main kernel: 2 consecutive-sorted boxes per block (R2d-proven loop)
//   3) blockIdx stride-148 interleave -> each SM sweeps a contiguous sorted
//      range; within-launch L1 persistence captures neighbor-box reuse.

namespace {

constexpr int Hh    = 64;
constexpr int Ww    = 64;
constexpr int Cc    = 1152;   // total channels
constexpr int Csz   = 128;    // channels per bin (Cc / 9)
constexpr int NSAMP = 81;     // 9 bins * 9 crop samples
constexpr int NWARP = 4;      // warps per box
constexpr int GBOX  = 2;      // boxes per block
constexpr int NSM   = 148;    // B200 SM count (bid -> SM round-robin)
constexpr int MAXBOX = 8192;

__device__ int g_order[MAXBOX + 1];

// ---- Sort kernel: single block, bucket boxes by (image, 8x8 center bucket) ----
__global__ __launch_bounds__(512) void sort_boxes_kernel(
    const float* __restrict__ boxes, int n, int nPerImage)
{
    __shared__ int s_cnt[512];
    __shared__ int s_ofs[512];
    __shared__ int s_scan[512];
    const int tid = threadIdx.x;

    s_cnt[tid] = 0;
    __syncthreads();

    // histogram
    for (int i = tid; i < n && i < MAXBOX; i += 512) {
        const float* bx = boxes + (size_t)i * 4;
        const float cy = (bx[0] + bx[2]) * 0.5f;
        const float cx = (bx[1] + bx[3]) * 0.5f;
        const int ky = min(7, max(0, (int)(cy * 8.0f)));
        const int kx = min(7, max(0, (int)(cx * 8.0f)));
        const int img = i / nPerImage;
        const int key = ((img & 7) << 6) | (ky << 3) | kx;
        atomicAdd(&s_cnt[key], 1);
    }
    __syncthreads();

    // inclusive scan (Hillis-Steele, 512 threads, 9 steps)
    s_scan[tid] = s_cnt[tid];
    __syncthreads();
    for (int d = 1; d < 512; d <<= 1) {
        int v = s_scan[tid];
        if (tid >= d) v += s_scan[tid - d];
        __syncthreads();
        s_scan[tid] = v;
        __syncthreads();
    }
    s_ofs[tid] = s_scan[tid] - s_cnt[tid];   // exclusive
    __syncthreads();

    // scatter
    for (int i = tid; i < n && i < MAXBOX; i += 512) {
        const float* bx = boxes + (size_t)i * 4;
        const float cy = (bx[0] + bx[2]) * 0.5f;
        const float cx = (bx[1] + bx[3]) * 0.5f;
        const int ky = min(7, max(0, (int)(cy * 8.0f)));
        const int kx = min(7, max(0, (int)(cx * 8.0f)));
        const int img = i / nPerImage;
        const int key = ((img & 7) << 6) | (ky << 3) | kx;
        const int pos = atomicAdd(&s_ofs[key], 1);
        g_order[pos] = i;
    }
    if (tid == 0) g_order[n] = 0;  // pad slot for odd n (rewrites box 0, benign)
}

// ---- Main kernel: 2 sorted boxes per block, 4 warps per box (R2d loop) ----
__global__ __launch_bounds__(GBOX * NWARP * 32, 4) void ps_pool_kernel(
    const float* __restrict__ img,    // [B, H, W, C]
    const float* __restrict__ boxes,  // [B*N, 4]
    const float* __restrict__ wts,    // [9]
    float* __restrict__ out,          // [B*N, 128]
    int nPerImage, int numGroups, int smCols)
{
    __shared__ int4   s_off[GBOX][NSAMP];
    __shared__ float4 s_w[GBOX][NSAMP];
    __shared__ float4 s_red[GBOX][NWARP][32];

    // stride-148 interleave: SM s sweeps contiguous sorted groups [s*smCols, ...)
    const int bid = blockIdx.x;
    const int g   = (bid % NSM) * smCols + bid / NSM;
    if (g >= numGroups) return;

    const int tid  = threadIdx.x;
    const int half = tid >> 7;          // which box (0/1)
    const int ht   = tid & 127;         // thread within half
    const int lane = tid & 31;
    const int warp = ht >> 5;           // warp within half (0..3)

    const int box_id = g_order[g * GBOX + half];
    const int b      = box_id / nPerImage;
    const float* __restrict__ image = img + (size_t)b * (Hh * Ww * Cc);
    const float* bx = boxes + (size_t)box_id * 4;

    // ---- per-box sample setup (81 threads of each half) ----
    if (ht < NSAMP) {
        const float y1 = bx[0], x1 = bx[1], y2 = bx[2], x2 = bx[3];
        const float step_y = (y2 - y1) * (1.0f / 3.0f);
        const float step_x = (x2 - x1) * (1.0f / 3.0f);

        const int s   = ht;
        const int by  = s / 27;
        const int bxn = (s / 9) % 3;
        const int py  = (s / 3) % 3;
        const int px  = s % 3;

        const float yy = (y1 + ((float)by + (float)py * 0.5f) * step_y) * (float)(Hh - 1);
        const float xx = (x1 + ((float)bxn + (float)px * 0.5f) * step_x) * (float)(Ww - 1);

        const float y0f = floorf(yy);
        const float x0f = floorf(xx);
        const float wy = yy - y0f;
        const float wx = xx - x0f;
        const int y0 = (int)y0f;
        const int x0 = (int)x0f;

        const int y0c = min(max(y0,     0), Hh - 1);
        const int y1c = min(max(y0 + 1, 0), Hh - 1);
        const int x0c = min(max(x0,     0), Ww - 1);
        const int x1c = min(max(x0 + 1, 0), Ww - 1);

        const bool inside = (yy >= 0.0f) && (yy <= (float)(Hh - 1)) &&
                            (xx >= 0.0f) && (xx <= (float)(Ww - 1));
        const int bin = by * 3 + bxn;
        const float wb = inside ? wts[bin] : 0.0f;
        const int cb = bin * Csz;

        s_off[half][s] = make_int4(((y0c * Ww + x0c) * Cc + cb) * 4,
                                   ((y0c * Ww + x1c) * Cc + cb) * 4,
                                   ((y1c * Ww + x0c) * Cc + cb) * 4,
                                   ((y1c * Ww + x1c) * Cc + cb) * 4);
        s_w[half][s] = make_float4(wb * (1.0f - wy) * (1.0f - wx),
                                   wb * (1.0f - wy) * wx,
                                   wb * wy * (1.0f - wx),
                                   wb * wy * wx);
    }
    __syncthreads();

    // ---- gather: 4 warps per box, samples split across warps ----
    const char* __restrict__ base = (const char*)image + lane * 16;
    const int s_begin = (warp * NSAMP) / NWARP;
    const int s_end   = ((warp + 1) * NSAMP) / NWARP;

    float4 acc = make_float4(0.f, 0.f, 0.f, 0.f);

    #pragma unroll 4
    for (int s = s_begin; s < s_end; s++) {
        const int4   off = s_off[half][s];
        const float4 w   = s_w[half][s];
        const float4 v0 = __ldg((const float4*)(base + off.x));
        const float4 v1 = __ldg((const float4*)(base + off.y));
        const float4 v2 = __ldg((const float4*)(base + off.z));
        const float4 v3 = __ldg((const float4*)(base + off.w));
        acc.x += w.x * v0.x + w.y * v1.x + w.z * v2.x + w.w * v3.x;
        acc.y += w.x * v0.y + w.y * v1.y + w.z * v2.y + w.w * v3.y;
        acc.z += w.x * v0.z + w.y * v1.z + w.z * v2.z + w.w * v3.z;
        acc.w += w.x * v0.w + w.y * v1.w + w.z * v2.w + w.w * v3.w;
    }

    s_red[half][warp][lane] = acc;
    __syncthreads();

    // ---- warp 0 of each half reduces + writes its box ----
    if (warp == 0) {
        float4 a0 = s_red[half][0][lane];
        float4 a1 = s_red[half][1][lane];
        float4 a2 = s_red[half][2][lane];
        float4 a3 = s_red[half][3][lane];
        const float inv = 1.0f / 81.0f;
        float4 o;
        o.x = (a0.x + a1.x + a2.x + a3.x) * inv;
        o.y = (a0.y + a1.y + a2.y + a3.y) * inv;
        o.z = (a0.z + a1.z + a2.z + a3.z) * inv;
        o.w = (a0.w + a1.w + a2.w + a3.w) * inv;
        reinterpret_cast<float4*>(out)[(size_t)box_id * (Csz / 4) + lane] = o;
    }
}

} // namespace

extern "C" void kernel_launch(void* const* d_in, const int* in_sizes, int n_in,
                              void* d_out, int out_size) {
    const float* img   = (const float*)d_in[0];  // [B,64,64,1152] fp32
    const float* boxes = (const float*)d_in[1];  // [B,N,4] fp32
    const float* wts   = (const float*)d_in[2];  // [9] fp32
    float* out = (float*)d_out;                  // [B*N, 128] fp32

    const int B          = in_sizes[0] / (Hh * Ww * Cc);
    const int totalBoxes = in_sizes[1] / 4;
    const int nPerImage  = totalBoxes / B;

    sort_boxes_kernel<<<1, 512>>>(boxes, totalBoxes, nPerImage);

    const int numGroups = (totalBoxes + GBOX - 1) / GBOX;
    const int smCols    = (numGroups + NSM - 1) / NSM;
    const int gridSize  = NSM * smCols;
    ps_pool_kernel<<<gridSize, GBOX * NWARP * 32>>>(
        img, boxes, wts, out, nPerImage, numGroups, smCols);
}